// round 12
// baseline (speedup 1.0000x reference)
#include <cuda_runtime.h>
#include <cuda_bf16.h>
#include <cstdint>

#define B_ 32
#define T_ 4096
#define H_ 512
#define GRID_ 128
#define THREADS_ 512

// h image: [buf][n][k] bf16 bits. n: 0-31 = h_hi per batch, 32-63 = h_lo. k = hidden unit.
__device__ __align__(128) unsigned short g_Bimg[2][64][512];
__device__ float    g_xT[T_ * B_];
__device__ __align__(128) unsigned g_flag[GRID_];   // per-CTA completed-step flags

__device__ __forceinline__ void stcg_u16(unsigned short* p, unsigned short v) {
    asm volatile("st.global.cg.u16 [%0], %1;" :: "l"(p), "h"(v));
}
__device__ __forceinline__ unsigned long long ld_acq64(const unsigned long long* p) {
    unsigned long long v;
    asm volatile("ld.acquire.gpu.global.b64 %0, [%1];" : "=l"(v) : "l"(p));
    return v;
}
__device__ __forceinline__ void st_rel_gpu(unsigned* p, unsigned v) {
    asm volatile("st.release.gpu.global.u32 [%0], %1;" :: "l"(p), "r"(v));
}
__device__ __forceinline__ unsigned ld_acq_cta(const unsigned* p) {
    unsigned v; asm volatile("ld.acquire.cta.u32 %0, [%1];" : "=r"(v) : "l"(p)); return v;
}
__device__ __forceinline__ void st_rel_cta(unsigned* p, unsigned v) {
    asm volatile("st.release.cta.u32 [%0], %1;" :: "l"(p), "r"(v));
}
__device__ __forceinline__ float fsig(float x) {
    return __fdividef(1.0f, 1.0f + __expf(-x));
}
__device__ __forceinline__ float ftanh(float x) {
    return 1.0f - __fdividef(2.0f, 1.0f + __expf(2.0f * x));
}
__device__ __forceinline__ uint32_t pack2(__nv_bfloat16 e0, __nv_bfloat16 e1) {
    unsigned short s0 = *(unsigned short*)&e0, s1 = *(unsigned short*)&e1;
    return (uint32_t)s0 | ((uint32_t)s1 << 16);
}
__device__ __forceinline__ uint32_t lds32(uint32_t a) {
    uint32_t v; asm volatile("ld.shared.b32 %0, [%1];" : "=r"(v) : "r"(a)); return v;
}
__device__ __forceinline__ uint32_t smem_u32(const void* p) {
    uint32_t a;
    asm("{ .reg .u64 t; cvta.to.shared.u64 t, %1; cvt.u32.u64 %0, t; }" : "=r"(a) : "l"(p));
    return a;
}
__device__ __forceinline__ void cp_async16(uint32_t dst, const void* src) {
    asm volatile("cp.async.cg.shared.global [%0], [%1], 16;" :: "r"(dst), "l"(src) : "memory");
}
__device__ __forceinline__ void cp_commit_wait() {
    asm volatile("cp.async.commit_group;" ::: "memory");
    asm volatile("cp.async.wait_group 0;" ::: "memory");
}

#define HMMA(d, a, b0r, b1r) \
    asm volatile("mma.sync.aligned.m16n8k16.row.col.f32.bf16.bf16.f32 " \
        "{%0,%1,%2,%3}, {%4,%5,%6,%7}, {%8,%9}, {%0,%1,%2,%3};" \
        : "+f"(d[0]), "+f"(d[1]), "+f"(d[2]), "+f"(d[3]) \
        : "r"(a[0]), "r"(a[1]), "r"(a[2]), "r"(a[3]), "r"(b0r), "r"(b1r))

// per-warp staging: 16 rows x 272B (pitch 272 -> conflict-free fragment LDS)
#define WPITCH 272
#define WREG   (16 * WPITCH)    // 4352 B per warp
#define DYN_SMEM (16 * WREG)    // 69632 B

__global__ void init_kernel(const float* __restrict__ x) {
    int idx = blockIdx.x * blockDim.x + threadIdx.x;
    int stride = gridDim.x * blockDim.x;
    unsigned* bz = (unsigned*)&g_Bimg[0][0][0];
    for (int i = idx; i < 64 * 512 / 2; i += stride) bz[i] = 0u;   // h(-1) = 0
    for (int i = idx; i < T_ * B_; i += stride) {
        int t = i >> 5, b = i & 31;
        g_xT[i] = x[(size_t)b * T_ + t];
    }
    if (idx < GRID_) g_flag[idx] = 0u;
}

__global__ void __launch_bounds__(THREADS_, 1) lstm_kernel(
    const float* __restrict__ Wih,
    const float* __restrict__ Whh,
    const float* __restrict__ bih,
    const float* __restrict__ bhh,
    float* __restrict__ out,
    int write_final)
{
    extern __shared__ unsigned char dyn[];
    __shared__ float sPart[2][4][16][33];  // [buf][ki][gate-row][batch(+pad)]
    __shared__ float sOut[128];            // [b][u]
    __shared__ unsigned s_gen;

    const int tid  = threadIdx.x;
    const int warp = tid >> 5;
    const int lane = tid & 31;
    const int g    = lane >> 2;   // fragment groupID
    const int tq   = lane & 3;    // fragment threadID_in_group
    const int cta  = blockIdx.x;
    const int nq   = warp & 3;    // batch-col octet: cols 8nq..8nq+7 (+ lo pair)
    const int ki   = warp >> 2;   // K-split 0..3 (K128 each)
    const int kbase = ki * 128;

    const uint32_t wreg = smem_u32(dyn) + warp * WREG;

    // ---- prologue: resident A fragments, hi set mt=0, lo set mt=1 ----
    uint32_t A[2][8][4];
#pragma unroll
    for (int mt = 0; mt < 2; mt++) {
#pragma unroll
        for (int kt = 0; kt < 8; kt++) {
            int k0 = kbase + kt * 16 + 2 * tq;
#pragma unroll
            for (int rg = 0; rg < 4; rg++) {
                int gr = (rg & 1) ? g + 8 : g;          // gate row 0..15
                int kk = k0 + ((rg >> 1) ? 8 : 0);
                int q = gr >> 2, u = gr & 3;
                const float* wp = &Whh[(size_t)(q * H_ + cta * 4 + u) * H_ + kk];
                float w0 = wp[0], w1 = wp[1];
                __nv_bfloat16 h0 = __float2bfloat16(w0);
                __nv_bfloat16 h1 = __float2bfloat16(w1);
                if (mt) {
                    h0 = __float2bfloat16(w0 - __bfloat162float(h0));
                    h1 = __float2bfloat16(w1 - __bfloat162float(h1));
                }
                A[mt][kt][rg] = pack2(h0, h1);
            }
        }
    }

    // pointwise constants + persistent state (consumers: warps 0-3 -> u=warp, b=lane)
    const int u = warp;
    const int b = lane;
    const int gu = cta * 4 + u;
    float wih[4], bias[4];
    float h_loc = 0.0f, c_loc = 0.0f;
    if (tid < 128) {
#pragma unroll
        for (int q = 0; q < 4; q++) {
            wih[q]  = Wih[q * H_ + gu];
            bias[q] = bih[q * H_ + gu] + bhh[q * H_ + gu];
        }
    }
    if (tid == 0) s_gen = 0u;
    __syncthreads();

    // stage row -> global n: rows 0-7 = 8nq+r (hhi), rows 8-15 = 32+8nq+(r-8) (hlo)
    const int srow = lane >> 4;             // 0/1: which of 2 rows this lane covers per iter
    const int soff = (lane & 15) * 16;      // byte offset in the 256B row slice

    const unsigned long long* f64 = (const unsigned long long*)g_flag;

    for (int t = 0; t < T_; t++) {
        const int p = t & 1;

        // ---- step gate: warp15 does a lane-parallel acquire scan of all 128 flags ----
        if (warp == 15) {
            const unsigned tu = (unsigned)t;
            for (;;) {
                unsigned long long a = ld_acq64(&f64[lane * 2]);
                unsigned long long c = ld_acq64(&f64[lane * 2 + 1]);
                bool ok = ((unsigned)a >= tu) && ((unsigned)(a >> 32) >= tu)
                       && ((unsigned)c >= tu) && ((unsigned)(c >> 32) >= tu);
                if (__all_sync(0xffffffffu, ok)) break;
            }
            if (lane == 0) st_rel_cta(&s_gen, tu);
            __syncwarp();
        } else {
            while (ld_acq_cta(&s_gen) < (unsigned)t) { }
        }

        float xv = 0.0f;
        if (tid < 128) xv = g_xT[t * B_ + b];

        // ---- stage 4KB B slice via cp.async (coalesced 16B, no reg round-trip) ----
        const unsigned char* img = (const unsigned char*)&g_Bimg[p][0][0] + kbase * 2;
#pragma unroll
        for (int it = 0; it < 8; it++) {
            int row = it * 2 + srow;                      // 0..15
            int n = (row < 8) ? (8 * nq + row) : (24 + 8 * nq + row);
            cp_async16(wreg + row * WPITCH + soff, img + (size_t)n * 1024 + soff);
        }
        cp_commit_wait();
        __syncwarp();

        // ---- MMA: K128, 2 m-tiles (hi/lo) x 2 n-tiles (hhi/hlo) ----
        float D[2][2][4];
#pragma unroll
        for (int mt = 0; mt < 2; mt++)
#pragma unroll
            for (int nt = 0; nt < 2; nt++)
#pragma unroll
                for (int e = 0; e < 4; e++) D[mt][nt][e] = 0.0f;

#pragma unroll
        for (int kt = 0; kt < 8; kt++) {
            uint32_t Bv[2][2];
#pragma unroll
            for (int nt = 0; nt < 2; nt++) {
                uint32_t a = wreg + (nt * 8 + g) * WPITCH + kt * 32 + tq * 4;
                Bv[nt][0] = lds32(a);
                Bv[nt][1] = lds32(a + 16);
            }
            HMMA(D[0][0], A[0][kt], Bv[0][0], Bv[0][1]);
            HMMA(D[0][1], A[0][kt], Bv[1][0], Bv[1][1]);
            HMMA(D[1][0], A[1][kt], Bv[0][0], Bv[0][1]);
            HMMA(D[1][1], A[1][kt], Bv[1][0], Bv[1][1]);
        }

        // ---- fold hi/lo (mt) and hhi/hlo (nt), STS partials ----
        {
            float f0 = (D[0][0][0] + D[1][0][0]) + (D[0][1][0] + D[1][1][0]);
            float f1 = (D[0][0][1] + D[1][0][1]) + (D[0][1][1] + D[1][1][1]);
            float f2 = (D[0][0][2] + D[1][0][2]) + (D[0][1][2] + D[1][1][2]);
            float f3 = (D[0][0][3] + D[1][0][3]) + (D[0][1][3] + D[1][1][3]);
            int colb = 8 * nq + 2 * tq;
            sPart[p][ki][g][colb]         = f0;
            sPart[p][ki][g][colb + 1]     = f1;
            sPart[p][ki][g + 8][colb]     = f2;
            sPart[p][ki][g + 8][colb + 1] = f3;
        }

        if (warp >= 4) {
            // producers: signal and run ahead to step t+1
            asm volatile("bar.arrive 2, %0;" :: "n"(THREADS_) : "memory");
        } else {
            asm volatile("bar.sync 2, %0;" :: "n"(THREADS_) : "memory");

            // ---- reduce over 4 k-splits + pointwise ----
            float g4[4];
#pragma unroll
            for (int q = 0; q < 4; q++) {
                int r = q * 4 + u;
                g4[q] = (sPart[p][0][r][b] + sPart[p][1][r][b])
                      + (sPart[p][2][r][b] + sPart[p][3][r][b])
                      + fmaf(xv, wih[q], bias[q]);
            }
            float is = fsig(g4[0]);
            float fs = fsig(g4[1]);
            float gs = ftanh(g4[2]);
            float os = fsig(g4[3]);
            float cn = fs * c_loc + is * gs;
            float hn = os * ftanh(cn);
            h_loc = 0.5f * (h_loc + hn);
            c_loc = 0.5f * (c_loc + cn);

            // publish h as bf16 hi/lo into next h image
            __nv_bfloat16 hh = __float2bfloat16(h_loc);
            __nv_bfloat16 hl = __float2bfloat16(h_loc - __bfloat162float(hh));
            stcg_u16(&g_Bimg[p ^ 1][b][gu],      *(unsigned short*)&hh);
            stcg_u16(&g_Bimg[p ^ 1][32 + b][gu], *(unsigned short*)&hl);
            sOut[b * 4 + u] = h_loc;

            if (write_final && t == T_ - 1) {
                float* o2 = out + (size_t)B_ * T_ * H_;
                o2[b * (2 * H_) + gu]      = h_loc;
                o2[b * (2 * H_) + H_ + gu] = c_loc;
            }

            asm volatile("bar.sync 1, 128;" ::: "memory");
            if (tid == 0) st_rel_gpu(&g_flag[cta], (unsigned)(t + 1));

            if (tid < 32) {  // coalesced v4 output store (off critical path)
                const float4 v = *(const float4*)(sOut + tid * 4);
                float* dst = out + ((size_t)tid * T_ + t) * H_ + cta * 4;
                asm volatile("st.global.cs.v4.f32 [%0], {%1,%2,%3,%4};"
                             :: "l"(dst), "f"(v.x), "f"(v.y), "f"(v.z), "f"(v.w));
            }
        }
    }
}

extern "C" void kernel_launch(void* const* d_in, const int* in_sizes, int n_in,
                              void* d_out, int out_size)
{
    const float* x   = (const float*)d_in[0];
    const float* Wih = (const float*)d_in[1];
    const float* Whh = (const float*)d_in[2];
    const float* bih = (const float*)d_in[3];
    const float* bhh = (const float*)d_in[4];
    float* out = (float*)d_out;

    int need = B_ * T_ * H_ + B_ * 2 * H_;
    int write_final = (out_size >= need) ? 1 : 0;

    static int smem_set = 0;
    if (!smem_set) {
        cudaFuncSetAttribute(lstm_kernel,
                             cudaFuncAttributeMaxDynamicSharedMemorySize,
                             DYN_SMEM);
        smem_set = 1;
    }

    init_kernel<<<256, 512>>>(x);
    lstm_kernel<<<GRID_, THREADS_, DYN_SMEM>>>(Wih, Whh, bih, bhh, out, write_final);
}

// round 13
// speedup vs baseline: 2.7895x; 2.7895x over previous
#include <cuda_runtime.h>
#include <cuda_bf16.h>
#include <cstdint>

#define B_ 32
#define T_ 4096
#define H_ 512
#define GRID_ 128
#define THREADS_ 512

// fragment-ordered h image: u32 idx = (((ki*4+nq)*8+kt)*32+lane)*4 + nt*2 + which
// (ki: K-quarter, nq: batch octet, kt: k16 block, lane=g*4+tq, nt: hi/lo, which: b0/b1)
__device__ __align__(128) uint32_t g_Bimg[2][16384];   // 64KB per buffer
__device__ float    g_xT[T_ * B_];
__device__ unsigned g_count;

__device__ __forceinline__ uint4 ldcg_v4(const void* p) {
    uint4 v;
    asm volatile("ld.global.cg.v4.b32 {%0,%1,%2,%3}, [%4];"
                 : "=r"(v.x), "=r"(v.y), "=r"(v.z), "=r"(v.w) : "l"(p));
    return v;
}
__device__ __forceinline__ void stcg_u16(void* p, unsigned short v) {
    asm volatile("st.global.cg.u16 [%0], %1;" :: "l"(p), "h"(v));
}
__device__ __forceinline__ unsigned ld_acq(const unsigned* p) {
    unsigned v; asm volatile("ld.acquire.gpu.global.u32 %0, [%1];" : "=r"(v) : "l"(p)); return v;
}
__device__ __forceinline__ void red_rel_add1(unsigned* p) {
    asm volatile("red.release.gpu.global.add.u32 [%0], 1;" :: "l"(p));
}
__device__ __forceinline__ unsigned ld_acq_cta(const unsigned* p) {
    unsigned v; asm volatile("ld.acquire.cta.u32 %0, [%1];" : "=r"(v) : "l"(p)); return v;
}
__device__ __forceinline__ void st_rel_cta(unsigned* p, unsigned v) {
    asm volatile("st.release.cta.u32 [%0], %1;" :: "l"(p), "r"(v));
}
__device__ __forceinline__ float fsig(float x) {
    return __fdividef(1.0f, 1.0f + __expf(-x));
}
__device__ __forceinline__ float ftanh(float x) {
    return 1.0f - __fdividef(2.0f, 1.0f + __expf(2.0f * x));
}
__device__ __forceinline__ uint32_t pack2(__nv_bfloat16 e0, __nv_bfloat16 e1) {
    unsigned short s0 = *(unsigned short*)&e0, s1 = *(unsigned short*)&e1;
    return (uint32_t)s0 | ((uint32_t)s1 << 16);
}

#define HMMA(d, a, b0r, b1r) \
    asm volatile("mma.sync.aligned.m16n8k16.row.col.f32.bf16.bf16.f32 " \
        "{%0,%1,%2,%3}, {%4,%5,%6,%7}, {%8,%9}, {%0,%1,%2,%3};" \
        : "+f"(d[0]), "+f"(d[1]), "+f"(d[2]), "+f"(d[3]) \
        : "r"(a[0]), "r"(a[1]), "r"(a[2]), "r"(a[3]), "r"(b0r), "r"(b1r))

__global__ void init_kernel(const float* __restrict__ x) {
    int idx = blockIdx.x * blockDim.x + threadIdx.x;
    int stride = gridDim.x * blockDim.x;
    for (int i = idx; i < 2 * 16384; i += stride) g_Bimg[0][i] = 0u;  // h(-1) = 0 (both bufs)
    for (int i = idx; i < T_ * B_; i += stride) {
        int t = i >> 5, b = i & 31;
        g_xT[i] = x[(size_t)b * T_ + t];
    }
    if (idx == 0) g_count = 0u;
}

__global__ void __launch_bounds__(THREADS_, 1) lstm_kernel(
    const float* __restrict__ Wih,
    const float* __restrict__ Whh,
    const float* __restrict__ bih,
    const float* __restrict__ bhh,
    float* __restrict__ out,
    int write_final)
{
    __shared__ float sPart[2][4][16][33];  // [buf][ki][gate-row][batch(+pad)]
    __shared__ float sOut[128];            // [b][u]
    __shared__ unsigned s_gen;

    const int tid  = threadIdx.x;
    const int warp = tid >> 5;
    const int lane = tid & 31;
    const int g    = lane >> 2;   // fragment groupID
    const int tq   = lane & 3;    // fragment threadID_in_group
    const int cta  = blockIdx.x;
    const int nq   = warp & 3;    // batch octet: b = 8nq..8nq+7
    const int ki   = warp >> 2;   // K-quarter (K128 each)
    const int kbase = ki * 128;

    // producer fragment-image byte base for this lane (per kt: +512B)
    const uint32_t fbase = (uint32_t)(((ki * 4 + nq) * 8) * 512 + lane * 16);

    // ---- prologue: resident A fragments, hi set mt=0, lo set mt=1 ----
    uint32_t A[2][8][4];
#pragma unroll
    for (int mt = 0; mt < 2; mt++) {
#pragma unroll
        for (int kt = 0; kt < 8; kt++) {
            int k0 = kbase + kt * 16 + 2 * tq;
#pragma unroll
            for (int rg = 0; rg < 4; rg++) {
                int gr = (rg & 1) ? g + 8 : g;          // gate row 0..15
                int kk = k0 + ((rg >> 1) ? 8 : 0);
                int q = gr >> 2, u = gr & 3;
                const float* wp = &Whh[(size_t)(q * H_ + cta * 4 + u) * H_ + kk];
                float w0 = wp[0], w1 = wp[1];
                __nv_bfloat16 h0 = __float2bfloat16(w0);
                __nv_bfloat16 h1 = __float2bfloat16(w1);
                if (mt) {
                    h0 = __float2bfloat16(w0 - __bfloat162float(h0));
                    h1 = __float2bfloat16(w1 - __bfloat162float(h1));
                }
                A[mt][kt][rg] = pack2(h0, h1);
            }
        }
    }

    // consumers: warps 0-3 -> unit u=warp, batch b=lane
    const int u = warp;
    const int b = lane;
    const int gu = cta * 4 + u;
    float wih[4], bias[4];
    float h_loc = 0.0f, c_loc = 0.0f;
    uint32_t off_hi = 0;
    if (tid < 128) {
#pragma unroll
        for (int q = 0; q < 4; q++) {
            wih[q]  = Wih[q * H_ + gu];
            bias[q] = bih[q * H_ + gu] + bhh[q * H_ + gu];
        }
        // publish offsets: value h[b][gu] -> fragment coordinates
        int kiC = gu >> 7, kl = gu & 127, ktC = kl >> 4, k16 = kl & 15;
        int whichC = k16 >> 3, tq2 = (k16 & 7) >> 1, parC = k16 & 1;
        int laneC = (b & 7) * 4 + tq2;
        int nqC = b >> 3;
        uint32_t idx = (uint32_t)((((kiC * 4 + nqC) * 8 + ktC) * 32 + laneC) * 4 + whichC);
        off_hi = idx * 4 + (uint32_t)parC * 2;   // nt=0; lo = +8 bytes
    }
    if (tid == 0) s_gen = 0u;
    __syncthreads();

    for (int t = 0; t < T_; t++) {
        const int p = t & 1;

        float xv = 0.0f;
        if (tid < 128) xv = g_xT[t * B_ + b];   // prefetch before gate

        // ---- step gate: warp15 lane0 polls counter, relays via smem ----
        if (warp == 15 && lane == 0) {
            while (ld_acq(&g_count) < (unsigned)GRID_ * (unsigned)t) { }
            st_rel_cta(&s_gen, (unsigned)t);
        }
        while (ld_acq_cta(&s_gen) < (unsigned)t) { }

        // ---- load B fragments directly (8x LDG.128, perfect sectors) + MMA ----
        const unsigned char* img = (const unsigned char*)g_Bimg[p] + fbase;
        uint4 V[8];
#pragma unroll
        for (int kt = 0; kt < 8; kt++) V[kt] = ldcg_v4(img + kt * 512);

        float D[2][2][4];
#pragma unroll
        for (int mt = 0; mt < 2; mt++)
#pragma unroll
            for (int nt = 0; nt < 2; nt++)
#pragma unroll
                for (int e = 0; e < 4; e++) D[mt][nt][e] = 0.0f;

#pragma unroll
        for (int kt = 0; kt < 8; kt++) {
            HMMA(D[0][0], A[0][kt], V[kt].x, V[kt].y);
            HMMA(D[0][1], A[0][kt], V[kt].z, V[kt].w);
            HMMA(D[1][0], A[1][kt], V[kt].x, V[kt].y);
            HMMA(D[1][1], A[1][kt], V[kt].z, V[kt].w);
        }

        // ---- fold hi/lo (mt) and hhi/hlo (nt), STS partials ----
        {
            float f0 = (D[0][0][0] + D[1][0][0]) + (D[0][1][0] + D[1][1][0]);
            float f1 = (D[0][0][1] + D[1][0][1]) + (D[0][1][1] + D[1][1][1]);
            float f2 = (D[0][0][2] + D[1][0][2]) + (D[0][1][2] + D[1][1][2]);
            float f3 = (D[0][0][3] + D[1][0][3]) + (D[0][1][3] + D[1][1][3]);
            int colb = 8 * nq + 2 * tq;
            sPart[p][ki][g][colb]         = f0;
            sPart[p][ki][g][colb + 1]     = f1;
            sPart[p][ki][g + 8][colb]     = f2;
            sPart[p][ki][g + 8][colb + 1] = f3;
        }

        if (warp >= 4) {
            // producers: signal and run ahead to step t+1
            asm volatile("bar.arrive 2, %0;" :: "n"(THREADS_) : "memory");
        } else {
            asm volatile("bar.sync 2, %0;" :: "n"(THREADS_) : "memory");

            // ---- reduce over 4 k-splits + pointwise ----
            float g4[4];
#pragma unroll
            for (int q = 0; q < 4; q++) {
                int r = q * 4 + u;
                g4[q] = (sPart[p][0][r][b] + sPart[p][1][r][b])
                      + (sPart[p][2][r][b] + sPart[p][3][r][b])
                      + fmaf(xv, wih[q], bias[q]);
            }
            float is = fsig(g4[0]);
            float fs = fsig(g4[1]);
            float gs = ftanh(g4[2]);
            float os = fsig(g4[3]);
            float cn = fs * c_loc + is * gs;
            float hn = os * ftanh(cn);
            h_loc = 0.5f * (h_loc + hn);
            c_loc = 0.5f * (c_loc + cn);

            // publish h (hi/lo) into next fragment image at constant offsets
            __nv_bfloat16 hh = __float2bfloat16(h_loc);
            __nv_bfloat16 hl = __float2bfloat16(h_loc - __bfloat162float(hh));
            unsigned char* nimg = (unsigned char*)g_Bimg[p ^ 1];
            stcg_u16(nimg + off_hi,     *(unsigned short*)&hh);
            stcg_u16(nimg + off_hi + 8, *(unsigned short*)&hl);

            asm volatile("bar.sync 1, 128;" ::: "memory");
            if (tid == 0) red_rel_add1(&g_count);

            // off-critical-path epilogue
            sOut[b * 4 + u] = h_loc;
            if (write_final && t == T_ - 1) {
                float* o2 = out + (size_t)B_ * T_ * H_;
                o2[b * (2 * H_) + gu]      = h_loc;
                o2[b * (2 * H_) + H_ + gu] = c_loc;
            }
            asm volatile("bar.sync 1, 128;" ::: "memory");

            if (tid < 32) {  // coalesced v4 output store
                const float4 v = *(const float4*)(sOut + tid * 4);
                float* dst = out + ((size_t)tid * T_ + t) * H_ + cta * 4;
                asm volatile("st.global.cs.v4.f32 [%0], {%1,%2,%3,%4};"
                             :: "l"(dst), "f"(v.x), "f"(v.y), "f"(v.z), "f"(v.w));
            }
        }
    }
}

extern "C" void kernel_launch(void* const* d_in, const int* in_sizes, int n_in,
                              void* d_out, int out_size)
{
    const float* x   = (const float*)d_in[0];
    const float* Wih = (const float*)d_in[1];
    const float* Whh = (const float*)d_in[2];
    const float* bih = (const float*)d_in[3];
    const float* bhh = (const float*)d_in[4];
    float* out = (float*)d_out;

    int need = B_ * T_ * H_ + B_ * 2 * H_;
    int write_final = (out_size >= need) ? 1 : 0;

    init_kernel<<<256, 512>>>(x);
    lstm_kernel<<<GRID_, THREADS_>>>(Wih, Whh, bih, bhh, out, write_final);
}

// round 14
// speedup vs baseline: 2.8479x; 1.0209x over previous
#include <cuda_runtime.h>
#include <cuda_bf16.h>
#include <cstdint>

#define B_ 32
#define T_ 4096
#define H_ 512
#define GRID_ 128
#define THREADS_ 512

// fragment-ordered h image: u32 idx = (((ki*4+nq)*8+kt)*32+lane)*4 + nt*2 + which
__device__ __align__(128) uint32_t g_Bimg[2][16384];   // 64KB per buffer
__device__ float    g_xT[T_ * B_];
__device__ unsigned g_count;

__device__ __forceinline__ uint4 ldcg_v4(const void* p) {
    uint4 v;
    asm volatile("ld.global.cg.v4.b32 {%0,%1,%2,%3}, [%4];"
                 : "=r"(v.x), "=r"(v.y), "=r"(v.z), "=r"(v.w) : "l"(p));
    return v;
}
__device__ __forceinline__ void stcg_u16(void* p, unsigned short v) {
    asm volatile("st.global.cg.u16 [%0], %1;" :: "l"(p), "h"(v));
}
__device__ __forceinline__ unsigned ld_acq(const unsigned* p) {
    unsigned v; asm volatile("ld.acquire.gpu.global.u32 %0, [%1];" : "=r"(v) : "l"(p)); return v;
}
__device__ __forceinline__ void red_rel_add1(unsigned* p) {
    asm volatile("red.release.gpu.global.add.u32 [%0], 1;" :: "l"(p));
}
__device__ __forceinline__ unsigned ld_acq_cta(const unsigned* p) {
    unsigned v; asm volatile("ld.acquire.cta.u32 %0, [%1];" : "=r"(v) : "l"(p)); return v;
}
__device__ __forceinline__ void st_rel_cta(unsigned* p, unsigned v) {
    asm volatile("st.release.cta.u32 [%0], %1;" :: "l"(p), "r"(v));
}
__device__ __forceinline__ float fsig(float x) {
    return __fdividef(1.0f, 1.0f + __expf(-x));
}
__device__ __forceinline__ float ftanh(float x) {
    return 1.0f - __fdividef(2.0f, 1.0f + __expf(2.0f * x));
}
__device__ __forceinline__ uint32_t pack2(__nv_bfloat16 e0, __nv_bfloat16 e1) {
    unsigned short s0 = *(unsigned short*)&e0, s1 = *(unsigned short*)&e1;
    return (uint32_t)s0 | ((uint32_t)s1 << 16);
}

#define HMMA(d, a, b0r, b1r) \
    asm volatile("mma.sync.aligned.m16n8k16.row.col.f32.bf16.bf16.f32 " \
        "{%0,%1,%2,%3}, {%4,%5,%6,%7}, {%8,%9}, {%0,%1,%2,%3};" \
        : "+f"(d[0]), "+f"(d[1]), "+f"(d[2]), "+f"(d[3]) \
        : "r"(a[0]), "r"(a[1]), "r"(a[2]), "r"(a[3]), "r"(b0r), "r"(b1r))

__global__ void init_kernel(const float* __restrict__ x) {
    int idx = blockIdx.x * blockDim.x + threadIdx.x;
    int stride = gridDim.x * blockDim.x;
    for (int i = idx; i < 2 * 16384; i += stride) g_Bimg[0][i] = 0u;  // h(-1) = 0
    for (int i = idx; i < T_ * B_; i += stride) {
        int t = i >> 5, b = i & 31;
        g_xT[i] = x[(size_t)b * T_ + t];
    }
    if (idx == 0) g_count = 0u;
}

__global__ void __launch_bounds__(THREADS_, 1) lstm_kernel(
    const float* __restrict__ Wih,
    const float* __restrict__ Whh,
    const float* __restrict__ bih,
    const float* __restrict__ bhh,
    float* __restrict__ out,
    int write_final)
{
    __shared__ float sPart[2][4][16][33];  // [buf][ki][gate-row][batch(+pad)]
    __shared__ float sOut[128];            // [b][u]
    __shared__ unsigned s_gen;

    const int tid  = threadIdx.x;
    const int warp = tid >> 5;
    const int lane = tid & 31;
    const int g    = lane >> 2;   // fragment groupID
    const int tq   = lane & 3;    // fragment threadID_in_group
    const int cta  = blockIdx.x;
    const int nq   = warp & 3;    // batch octet
    const int ki   = warp >> 2;   // K-quarter (K128 each)
    const int kbase = ki * 128;

    // producer fragment-image byte base for this lane (per kt: +512B)
    const uint32_t fbase = (uint32_t)(((ki * 4 + nq) * 8) * 512 + lane * 16);

    // ---- prologue: resident A fragments, hi set mt=0, lo set mt=1 ----
    uint32_t A[2][8][4];
#pragma unroll
    for (int mt = 0; mt < 2; mt++) {
#pragma unroll
        for (int kt = 0; kt < 8; kt++) {
            int k0 = kbase + kt * 16 + 2 * tq;
#pragma unroll
            for (int rg = 0; rg < 4; rg++) {
                int gr = (rg & 1) ? g + 8 : g;          // gate row 0..15
                int kk = k0 + ((rg >> 1) ? 8 : 0);
                int q = gr >> 2, u = gr & 3;
                const float* wp = &Whh[(size_t)(q * H_ + cta * 4 + u) * H_ + kk];
                float w0 = wp[0], w1 = wp[1];
                __nv_bfloat16 h0 = __float2bfloat16(w0);
                __nv_bfloat16 h1 = __float2bfloat16(w1);
                if (mt) {
                    h0 = __float2bfloat16(w0 - __bfloat162float(h0));
                    h1 = __float2bfloat16(w1 - __bfloat162float(h1));
                }
                A[mt][kt][rg] = pack2(h0, h1);
            }
        }
    }

    // consumers: warps 0-3 -> unit u=warp, batch b=lane
    const int u = warp;
    const int b = lane;
    const int gu = cta * 4 + u;
    float wih[4], bias[4];
    float h_loc = 0.0f, c_loc = 0.0f;
    uint32_t off_hi = 0;
    if (tid < 128) {
#pragma unroll
        for (int q = 0; q < 4; q++) {
            wih[q]  = Wih[q * H_ + gu];
            bias[q] = bih[q * H_ + gu] + bhh[q * H_ + gu];
        }
        int kiC = gu >> 7, kl = gu & 127, ktC = kl >> 4, k16 = kl & 15;
        int whichC = k16 >> 3, tq2 = (k16 & 7) >> 1, parC = k16 & 1;
        int laneC = (b & 7) * 4 + tq2;
        int nqC = b >> 3;
        uint32_t idx = (uint32_t)((((kiC * 4 + nqC) * 8 + ktC) * 32 + laneC) * 4 + whichC);
        off_hi = idx * 4 + (uint32_t)parC * 2;   // nt=0; lo = +8 bytes
    }
    if (tid == 0) s_gen = 0u;
    __syncthreads();

    for (int t = 0; t < T_; t++) {
        const int p = t & 1;

        float xv = 0.0f;
        if (tid < 128) xv = g_xT[t * B_ + b];   // prefetch before gate

        // ---- step gate: warp15 lane0 polls counter, relays via smem ----
        if (warp == 15 && lane == 0) {
            while (ld_acq(&g_count) < (unsigned)GRID_ * (unsigned)t) { }
            st_rel_cta(&s_gen, (unsigned)t);
        }
        while (ld_acq_cta(&s_gen) < (unsigned)t) { }

        // ---- load B fragments directly (8x LDG.128) + MMA ----
        const unsigned char* img = (const unsigned char*)g_Bimg[p] + fbase;
        uint4 V[8];
#pragma unroll
        for (int kt = 0; kt < 8; kt++) V[kt] = ldcg_v4(img + kt * 512);

        // D accumulators: Whi*hhi, Whi*hlo, Wlo*hhi (Wlo*hlo ~2^-18, dropped)
        float D00[4], D01[4], D10[4];
#pragma unroll
        for (int e = 0; e < 4; e++) { D00[e] = 0.0f; D01[e] = 0.0f; D10[e] = 0.0f; }

#pragma unroll
        for (int kt = 0; kt < 8; kt++) {
            HMMA(D00, A[0][kt], V[kt].x, V[kt].y);
            HMMA(D01, A[0][kt], V[kt].z, V[kt].w);
            HMMA(D10, A[1][kt], V[kt].x, V[kt].y);
        }

        // ---- fold, STS partials ----
        {
            float f0 = (D00[0] + D01[0]) + D10[0];
            float f1 = (D00[1] + D01[1]) + D10[1];
            float f2 = (D00[2] + D01[2]) + D10[2];
            float f3 = (D00[3] + D01[3]) + D10[3];
            int colb = 8 * nq + 2 * tq;
            sPart[p][ki][g][colb]         = f0;
            sPart[p][ki][g][colb + 1]     = f1;
            sPart[p][ki][g + 8][colb]     = f2;
            sPart[p][ki][g + 8][colb + 1] = f3;
        }

        if (warp >= 4) {
            // producers: signal and run ahead to step t+1
            asm volatile("bar.arrive 2, %0;" :: "n"(THREADS_) : "memory");
        } else {
            asm volatile("bar.sync 2, %0;" :: "n"(THREADS_) : "memory");

            // ---- reduce over 4 k-splits + pointwise (critical path first) ----
            float g4[4];
#pragma unroll
            for (int q = 0; q < 4; q++) {
                int r = q * 4 + u;
                g4[q] = (sPart[p][0][r][b] + sPart[p][1][r][b])
                      + (sPart[p][2][r][b] + sPart[p][3][r][b])
                      + fmaf(xv, wih[q], bias[q]);
            }
            float is = fsig(g4[0]);
            float fs = fsig(g4[1]);
            float gs = ftanh(g4[2]);
            float os = fsig(g4[3]);
            float cn = fs * c_loc + is * gs;
            float hn = os * ftanh(cn);
            h_loc = 0.5f * (h_loc + hn);

            // publish h (hi/lo) FIRST — this is the global critical path
            __nv_bfloat16 hh = __float2bfloat16(h_loc);
            __nv_bfloat16 hl = __float2bfloat16(h_loc - __bfloat162float(hh));
            unsigned char* nimg = (unsigned char*)g_Bimg[p ^ 1];
            stcg_u16(nimg + off_hi,     *(unsigned short*)&hh);
            stcg_u16(nimg + off_hi + 8, *(unsigned short*)&hl);

            asm volatile("bar.sync 1, 128;" ::: "memory");
            if (tid == 0) red_rel_add1(&g_count);

            // ---- off-critical-path epilogue ----
            c_loc = 0.5f * (c_loc + cn);
            sOut[b * 4 + u] = h_loc;
            if (write_final && t == T_ - 1) {
                float* o2 = out + (size_t)B_ * T_ * H_;
                o2[b * (2 * H_) + gu]      = h_loc;
                o2[b * (2 * H_) + H_ + gu] = c_loc;
            }
            asm volatile("bar.sync 1, 128;" ::: "memory");

            if (tid < 32) {  // coalesced v4 output store
                const float4 v = *(const float4*)(sOut + tid * 4);
                float* dst = out + ((size_t)tid * T_ + t) * H_ + cta * 4;
                asm volatile("st.global.cs.v4.f32 [%0], {%1,%2,%3,%4};"
                             :: "l"(dst), "f"(v.x), "f"(v.y), "f"(v.z), "f"(v.w));
            }
        }
    }
}

extern "C" void kernel_launch(void* const* d_in, const int* in_sizes, int n_in,
                              void* d_out, int out_size)
{
    const float* x   = (const float*)d_in[0];
    const float* Wih = (const float*)d_in[1];
    const float* Whh = (const float*)d_in[2];
    const float* bih = (const float*)d_in[3];
    const float* bhh = (const float*)d_in[4];
    float* out = (float*)d_out;

    int need = B_ * T_ * H_ + B_ * 2 * H_;
    int write_final = (out_size >= need) ? 1 : 0;

    init_kernel<<<256, 512>>>(x);
    lstm_kernel<<<GRID_, THREADS_>>>(Wih, Whh, bih, bhh, out, write_final);
}

// round 15
// speedup vs baseline: 2.8552x; 1.0026x over previous
#include <cuda_runtime.h>
#include <cuda_bf16.h>
#include <cstdint>

#define B_ 32
#define T_ 4096
#define H_ 512
#define GRID_ 128
#define THREADS_ 512

// fragment-ordered h image: u32 idx = (((ki*4+nq)*8+kt)*32+lane)*4 + nt*2 + which
__device__ __align__(128) uint32_t g_Bimg[2][16384];   // 64KB per buffer
__device__ float    g_xT[T_ * B_];
__device__ __align__(128) unsigned g_cnt4[128];        // 4 quarter counters @ idx 0,32,64,96

__device__ __forceinline__ uint4 ldcg_v4(const void* p) {
    uint4 v;
    asm volatile("ld.global.cg.v4.b32 {%0,%1,%2,%3}, [%4];"
                 : "=r"(v.x), "=r"(v.y), "=r"(v.z), "=r"(v.w) : "l"(p));
    return v;
}
__device__ __forceinline__ void stcg_u16(void* p, unsigned short v) {
    asm volatile("st.global.cg.u16 [%0], %1;" :: "l"(p), "h"(v));
}
__device__ __forceinline__ unsigned ld_acq(const unsigned* p) {
    unsigned v; asm volatile("ld.acquire.gpu.global.u32 %0, [%1];" : "=r"(v) : "l"(p)); return v;
}
__device__ __forceinline__ void red_rel_add1(unsigned* p) {
    asm volatile("red.release.gpu.global.add.u32 [%0], 1;" :: "l"(p));
}
__device__ __forceinline__ unsigned ld_acq_cta(const unsigned* p) {
    unsigned v; asm volatile("ld.acquire.cta.u32 %0, [%1];" : "=r"(v) : "l"(p)); return v;
}
__device__ __forceinline__ void st_rel_cta(unsigned* p, unsigned v) {
    asm volatile("st.release.cta.u32 [%0], %1;" :: "l"(p), "r"(v));
}
__device__ __forceinline__ float fsig(float x) {
    return __fdividef(1.0f, 1.0f + __expf(-x));
}
__device__ __forceinline__ float ftanh(float x) {
    return 1.0f - __fdividef(2.0f, 1.0f + __expf(2.0f * x));
}
__device__ __forceinline__ uint32_t pack2(__nv_bfloat16 e0, __nv_bfloat16 e1) {
    unsigned short s0 = *(unsigned short*)&e0, s1 = *(unsigned short*)&e1;
    return (uint32_t)s0 | ((uint32_t)s1 << 16);
}

#define HMMA(d, a, b0r, b1r) \
    asm volatile("mma.sync.aligned.m16n8k16.row.col.f32.bf16.bf16.f32 " \
        "{%0,%1,%2,%3}, {%4,%5,%6,%7}, {%8,%9}, {%0,%1,%2,%3};" \
        : "+f"(d[0]), "+f"(d[1]), "+f"(d[2]), "+f"(d[3]) \
        : "r"(a[0]), "r"(a[1]), "r"(a[2]), "r"(a[3]), "r"(b0r), "r"(b1r))

__global__ void init_kernel(const float* __restrict__ x) {
    int idx = blockIdx.x * blockDim.x + threadIdx.x;
    int stride = gridDim.x * blockDim.x;
    for (int i = idx; i < 2 * 16384; i += stride) g_Bimg[0][i] = 0u;  // h(-1) = 0
    for (int i = idx; i < T_ * B_; i += stride) {
        int t = i >> 5, b = i & 31;
        g_xT[i] = x[(size_t)b * T_ + t];
    }
    if (idx < 128) g_cnt4[idx] = 0u;
}

__global__ void __launch_bounds__(THREADS_, 1) lstm_kernel(
    const float* __restrict__ Wih,
    const float* __restrict__ Whh,
    const float* __restrict__ bih,
    const float* __restrict__ bhh,
    float* __restrict__ out,
    int write_final)
{
    __shared__ float sPart[2][4][16][33];  // [buf][ki][gate-row][batch(+pad)]
    __shared__ float sOut[128];            // [b][u]
    __shared__ unsigned s_genq[4];         // per-quarter step tokens

    const int tid  = threadIdx.x;
    const int warp = tid >> 5;
    const int lane = tid & 31;
    const int g    = lane >> 2;   // fragment groupID
    const int tq   = lane & 3;    // fragment threadID_in_group
    const int cta  = blockIdx.x;
    const int nq   = warp & 3;    // batch octet
    const int ki   = warp >> 2;   // K-quarter (K128 each)
    const int kbase = ki * 128;

    // producer fragment-image byte base for this lane (per kt: +512B)
    const uint32_t fbase = (uint32_t)(((ki * 4 + nq) * 8) * 512 + lane * 16);

    // ---- prologue: resident A fragments, hi set mt=0, lo set mt=1 ----
    uint32_t A[2][8][4];
#pragma unroll
    for (int mt = 0; mt < 2; mt++) {
#pragma unroll
        for (int kt = 0; kt < 8; kt++) {
            int k0 = kbase + kt * 16 + 2 * tq;
#pragma unroll
            for (int rg = 0; rg < 4; rg++) {
                int gr = (rg & 1) ? g + 8 : g;          // gate row 0..15
                int kk = k0 + ((rg >> 1) ? 8 : 0);
                int q = gr >> 2, u = gr & 3;
                const float* wp = &Whh[(size_t)(q * H_ + cta * 4 + u) * H_ + kk];
                float w0 = wp[0], w1 = wp[1];
                __nv_bfloat16 h0 = __float2bfloat16(w0);
                __nv_bfloat16 h1 = __float2bfloat16(w1);
                if (mt) {
                    h0 = __float2bfloat16(w0 - __bfloat162float(h0));
                    h1 = __float2bfloat16(w1 - __bfloat162float(h1));
                }
                A[mt][kt][rg] = pack2(h0, h1);
            }
        }
    }

    // consumers: warps 0-3 -> unit u=warp, batch b=lane
    const int u = warp;
    const int b = lane;
    const int gu = cta * 4 + u;
    float wih[4], bias[4];
    float h_loc = 0.0f, c_loc = 0.0f;
    uint32_t off_hi = 0;
    if (tid < 128) {
#pragma unroll
        for (int q = 0; q < 4; q++) {
            wih[q]  = Wih[q * H_ + gu];
            bias[q] = bih[q * H_ + gu] + bhh[q * H_ + gu];
        }
        int kiC = gu >> 7, kl = gu & 127, ktC = kl >> 4, k16 = kl & 15;
        int whichC = k16 >> 3, tq2 = (k16 & 7) >> 1, parC = k16 & 1;
        int laneC = (b & 7) * 4 + tq2;
        int nqC = b >> 3;
        uint32_t idx = (uint32_t)((((kiC * 4 + nqC) * 8 + ktC) * 32 + laneC) * 4 + whichC);
        off_hi = idx * 4 + (uint32_t)parC * 2;   // nt=0; lo = +8 bytes
    }
    if (tid < 4) s_genq[tid] = 0u;
    __syncthreads();

    // this CTA's quarter counter (units 4cta..4cta+3 all in quarter cta>>5)
    unsigned* mycnt = &g_cnt4[(cta >> 5) * 32];

    for (int t = 0; t < T_; t++) {
        const int p = t & 1;

        float xv = 0.0f;
        if (tid < 128) xv = g_xT[t * B_ + b];   // prefetch before gate

        // ---- quarter gate: warp15 lanes 0-3 poll the 4 counters, post tokens ----
        if (warp == 15) {
            if (lane < 4) {
                const unsigned* c = &g_cnt4[lane * 32];
                const unsigned tgt = 128u * (unsigned)t;   // 32 CTAs x 4 warp-releases
                while (ld_acq(c) < tgt) { }
                st_rel_cta(&s_genq[lane], (unsigned)t);
            }
            __syncwarp();   // warp15 proceeds once all quarters are in
        } else {
            while (ld_acq_cta(&s_genq[ki]) < (unsigned)t) { }
        }

        // ---- load B fragments directly (8x LDG.128) + MMA ----
        const unsigned char* img = (const unsigned char*)g_Bimg[p] + fbase;
        uint4 V[8];
#pragma unroll
        for (int kt = 0; kt < 8; kt++) V[kt] = ldcg_v4(img + kt * 512);

        // D accumulators: Whi*hhi, Whi*hlo, Wlo*hhi (Wlo*hlo dropped, ~2^-18)
        float D00[4], D01[4], D10[4];
#pragma unroll
        for (int e = 0; e < 4; e++) { D00[e] = 0.0f; D01[e] = 0.0f; D10[e] = 0.0f; }

#pragma unroll
        for (int kt = 0; kt < 8; kt++) {
            HMMA(D00, A[0][kt], V[kt].x, V[kt].y);
            HMMA(D01, A[0][kt], V[kt].z, V[kt].w);
            HMMA(D10, A[1][kt], V[kt].x, V[kt].y);
        }

        // ---- fold, STS partials ----
        {
            float f0 = (D00[0] + D01[0]) + D10[0];
            float f1 = (D00[1] + D01[1]) + D10[1];
            float f2 = (D00[2] + D01[2]) + D10[2];
            float f3 = (D00[3] + D01[3]) + D10[3];
            int colb = 8 * nq + 2 * tq;
            sPart[p][ki][g][colb]         = f0;
            sPart[p][ki][g][colb + 1]     = f1;
            sPart[p][ki][g + 8][colb]     = f2;
            sPart[p][ki][g + 8][colb + 1] = f3;
        }

        if (warp >= 4) {
            // producers: signal and run ahead to step t+1
            asm volatile("bar.arrive 2, %0;" :: "n"(THREADS_) : "memory");
        } else {
            asm volatile("bar.sync 2, %0;" :: "n"(THREADS_) : "memory");

            // ---- reduce over 4 k-splits + pointwise (critical path first) ----
            float g4[4];
#pragma unroll
            for (int q = 0; q < 4; q++) {
                int r = q * 4 + u;
                g4[q] = (sPart[p][0][r][b] + sPart[p][1][r][b])
                      + (sPart[p][2][r][b] + sPart[p][3][r][b])
                      + fmaf(xv, wih[q], bias[q]);
            }
            float is = fsig(g4[0]);
            float fs = fsig(g4[1]);
            float gs = ftanh(g4[2]);
            float os = fsig(g4[3]);
            float cn = fs * c_loc + is * gs;
            float hn = os * ftanh(cn);
            h_loc = 0.5f * (h_loc + hn);

            // publish h (hi/lo) and release THIS WARP immediately — no CTA barrier
            __nv_bfloat16 hh = __float2bfloat16(h_loc);
            __nv_bfloat16 hl = __float2bfloat16(h_loc - __bfloat162float(hh));
            unsigned char* nimg = (unsigned char*)g_Bimg[p ^ 1];
            stcg_u16(nimg + off_hi,     *(unsigned short*)&hh);
            stcg_u16(nimg + off_hi + 8, *(unsigned short*)&hl);
            __syncwarp();
            if (lane == 0) red_rel_add1(mycnt);

            // ---- off-critical-path epilogue ----
            c_loc = 0.5f * (c_loc + cn);
            sOut[b * 4 + u] = h_loc;
            if (write_final && t == T_ - 1) {
                float* o2 = out + (size_t)B_ * T_ * H_;
                o2[b * (2 * H_) + gu]      = h_loc;
                o2[b * (2 * H_) + H_ + gu] = c_loc;
            }
            asm volatile("bar.sync 1, 128;" ::: "memory");

            if (tid < 32) {  // coalesced v4 output store
                const float4 v = *(const float4*)(sOut + tid * 4);
                float* dst = out + ((size_t)tid * T_ + t) * H_ + cta * 4;
                asm volatile("st.global.cs.v4.f32 [%0], {%1,%2,%3,%4};"
                             :: "l"(dst), "f"(v.x), "f"(v.y), "f"(v.z), "f"(v.w));
            }
        }
    }
}

extern "C" void kernel_launch(void* const* d_in, const int* in_sizes, int n_in,
                              void* d_out, int out_size)
{
    const float* x   = (const float*)d_in[0];
    const float* Wih = (const float*)d_in[1];
    const float* Whh = (const float*)d_in[2];
    const float* bih = (const float*)d_in[3];
    const float* bhh = (const float*)d_in[4];
    float* out = (float*)d_out;

    int need = B_ * T_ * H_ + B_ * 2 * H_;
    int write_final = (out_size >= need) ? 1 : 0;

    init_kernel<<<256, 512>>>(x);
    lstm_kernel<<<GRID_, THREADS_>>>(Wih, Whh, bih, bhh, out, write_final);
}

// round 16
// speedup vs baseline: 3.2434x; 1.1360x over previous
#include <cuda_runtime.h>
#include <cuda_fp16.h>
#include <cstdint>

#define B_ 32
#define T_ 4096
#define H_ 512
#define GRID_ 128
#define THREADS_ 512

// fragment-ordered fp16 h image: u32 idx = (((ki*4+nq)*8+kt)*32+lane)*2 + which
__device__ __align__(128) uint32_t g_Bimg[2][8192];    // 32KB per buffer
__device__ float    g_xT[T_ * B_];
__device__ __align__(128) unsigned g_cnt4[128];        // 4 quarter counters @ idx 0,32,64,96

__device__ __forceinline__ uint2 ldcg_v2(const void* p) {
    uint2 v;
    asm volatile("ld.global.cg.v2.b32 {%0,%1}, [%2];"
                 : "=r"(v.x), "=r"(v.y) : "l"(p));
    return v;
}
__device__ __forceinline__ void stcg_u16(void* p, unsigned short v) {
    asm volatile("st.global.cg.u16 [%0], %1;" :: "l"(p), "h"(v));
}
__device__ __forceinline__ unsigned ld_acq(const unsigned* p) {
    unsigned v; asm volatile("ld.acquire.gpu.global.u32 %0, [%1];" : "=r"(v) : "l"(p)); return v;
}
__device__ __forceinline__ void red_rel_add1(unsigned* p) {
    asm volatile("red.release.gpu.global.add.u32 [%0], 1;" :: "l"(p));
}
__device__ __forceinline__ unsigned ld_acq_cta(const unsigned* p) {
    unsigned v; asm volatile("ld.acquire.cta.u32 %0, [%1];" : "=r"(v) : "l"(p)); return v;
}
__device__ __forceinline__ void st_rel_cta(unsigned* p, unsigned v) {
    asm volatile("st.release.cta.u32 [%0], %1;" :: "l"(p), "r"(v));
}
__device__ __forceinline__ float fsig(float x) {
    return __fdividef(1.0f, 1.0f + __expf(-x));
}
__device__ __forceinline__ float ftanh(float x) {
    return 1.0f - __fdividef(2.0f, 1.0f + __expf(2.0f * x));
}
__device__ __forceinline__ uint32_t pack2h(__half e0, __half e1) {
    unsigned short s0 = *(unsigned short*)&e0, s1 = *(unsigned short*)&e1;
    return (uint32_t)s0 | ((uint32_t)s1 << 16);
}

#define HMMA16(d, a, b0r, b1r) \
    asm volatile("mma.sync.aligned.m16n8k16.row.col.f32.f16.f16.f32 " \
        "{%0,%1,%2,%3}, {%4,%5,%6,%7}, {%8,%9}, {%0,%1,%2,%3};" \
        : "+f"(d[0]), "+f"(d[1]), "+f"(d[2]), "+f"(d[3]) \
        : "r"(a[0]), "r"(a[1]), "r"(a[2]), "r"(a[3]), "r"(b0r), "r"(b1r))

__global__ void init_kernel(const float* __restrict__ x) {
    int idx = blockIdx.x * blockDim.x + threadIdx.x;
    int stride = gridDim.x * blockDim.x;
    for (int i = idx; i < 2 * 8192; i += stride) g_Bimg[0][i] = 0u;   // h(-1) = 0
    for (int i = idx; i < T_ * B_; i += stride) {
        int t = i >> 5, b = i & 31;
        g_xT[i] = x[(size_t)b * T_ + t];
    }
    if (idx < 128) g_cnt4[idx] = 0u;
}

__global__ void __launch_bounds__(THREADS_, 1) lstm_kernel(
    const float* __restrict__ Wih,
    const float* __restrict__ Whh,
    const float* __restrict__ bih,
    const float* __restrict__ bhh,
    float* __restrict__ out,
    int write_final)
{
    __shared__ float sPart[2][4][16][33];  // [buf][ki][gate-row][batch(+pad)]
    __shared__ float sOut[128];            // [b][u]
    __shared__ unsigned s_genq[4];         // per-quarter step tokens

    const int tid  = threadIdx.x;
    const int warp = tid >> 5;
    const int lane = tid & 31;
    const int g    = lane >> 2;   // fragment groupID
    const int tq   = lane & 3;    // fragment threadID_in_group
    const int cta  = blockIdx.x;
    const int nq   = warp & 3;    // batch octet
    const int ki   = warp >> 2;   // K-quarter (K128 each)
    const int kbase = ki * 128;

    // producer fragment-image byte base for this lane (per kt: +256B)
    const uint32_t fbase = (uint32_t)(((ki * 4 + nq) * 8) * 256 + lane * 8);

    // ---- prologue: resident fp16 A fragments, hi set mt=0, lo set mt=1 ----
    uint32_t A[2][8][4];
#pragma unroll
    for (int mt = 0; mt < 2; mt++) {
#pragma unroll
        for (int kt = 0; kt < 8; kt++) {
            int k0 = kbase + kt * 16 + 2 * tq;
#pragma unroll
            for (int rg = 0; rg < 4; rg++) {
                int gr = (rg & 1) ? g + 8 : g;          // gate row 0..15
                int kk = k0 + ((rg >> 1) ? 8 : 0);
                int q = gr >> 2, u = gr & 3;
                const float* wp = &Whh[(size_t)(q * H_ + cta * 4 + u) * H_ + kk];
                float w0 = wp[0], w1 = wp[1];
                __half h0 = __float2half(w0);
                __half h1 = __float2half(w1);
                if (mt) {
                    h0 = __float2half(w0 - __half2float(h0));
                    h1 = __float2half(w1 - __half2float(h1));
                }
                A[mt][kt][rg] = pack2h(h0, h1);
            }
        }
    }

    // consumers: warps 0-3 -> unit u=warp, batch b=lane
    const int u = warp;
    const int b = lane;
    const int gu = cta * 4 + u;
    float wih[4], bias[4];
    float h_loc = 0.0f, c_loc = 0.0f;
    uint32_t off_h = 0;
    if (tid < 128) {
#pragma unroll
        for (int q = 0; q < 4; q++) {
            wih[q]  = Wih[q * H_ + gu];
            bias[q] = bih[q * H_ + gu] + bhh[q * H_ + gu];
        }
        // publish offset: value h[b][gu] -> fragment coordinates (single fp16)
        int kiC = gu >> 7, kl = gu & 127, ktC = kl >> 4, k16 = kl & 15;
        int whichC = k16 >> 3, tq2 = (k16 & 7) >> 1, parC = k16 & 1;
        int laneC = (b & 7) * 4 + tq2;
        int nqC = b >> 3;
        uint32_t idx = (uint32_t)((((kiC * 4 + nqC) * 8 + ktC) * 32 + laneC) * 2 + whichC);
        off_h = idx * 4 + (uint32_t)parC * 2;
    }
    if (tid < 4) s_genq[tid] = 0u;
    __syncthreads();

    // this CTA's quarter counter
    unsigned* mycnt = &g_cnt4[(cta >> 5) * 32];

    for (int t = 0; t < T_; t++) {
        const int p = t & 1;

        float xv = 0.0f;
        if (tid < 128) xv = g_xT[t * B_ + b];   // prefetch before gate

        // ---- quarter gate: warp15 lanes 0-3 poll the 4 counters, post tokens ----
        if (warp == 15) {
            if (lane < 4) {
                const unsigned* c = &g_cnt4[lane * 32];
                const unsigned tgt = 128u * (unsigned)t;   // 32 CTAs x 4 warp-releases
                while (ld_acq(c) < tgt) { }
                st_rel_cta(&s_genq[lane], (unsigned)t);
            }
            __syncwarp();
        } else {
            while (ld_acq_cta(&s_genq[ki]) < (unsigned)t) { }
        }

        // ---- load B fragments (8x LDG.64, contiguous 256B/kt) + MMA ----
        const unsigned char* img = (const unsigned char*)g_Bimg[p] + fbase;
        uint2 V[8];
#pragma unroll
        for (int kt = 0; kt < 8; kt++) V[kt] = ldcg_v2(img + kt * 256);

        // D accumulators: Whi*h, Wlo*h
        float D0[4], D1[4];
#pragma unroll
        for (int e = 0; e < 4; e++) { D0[e] = 0.0f; D1[e] = 0.0f; }

#pragma unroll
        for (int kt = 0; kt < 8; kt++) {
            HMMA16(D0, A[0][kt], V[kt].x, V[kt].y);
            HMMA16(D1, A[1][kt], V[kt].x, V[kt].y);
        }

        // ---- fold hi/lo, STS partials ----
        {
            float f0 = D0[0] + D1[0];
            float f1 = D0[1] + D1[1];
            float f2 = D0[2] + D1[2];
            float f3 = D0[3] + D1[3];
            int colb = 8 * nq + 2 * tq;
            sPart[p][ki][g][colb]         = f0;
            sPart[p][ki][g][colb + 1]     = f1;
            sPart[p][ki][g + 8][colb]     = f2;
            sPart[p][ki][g + 8][colb + 1] = f3;
        }

        if (warp >= 4) {
            // producers: signal and run ahead to step t+1
            asm volatile("bar.arrive 2, %0;" :: "n"(THREADS_) : "memory");
        } else {
            asm volatile("bar.sync 2, %0;" :: "n"(THREADS_) : "memory");

            // ---- reduce over 4 k-splits + pointwise (critical path first) ----
            float g4[4];
#pragma unroll
            for (int q = 0; q < 4; q++) {
                int r = q * 4 + u;
                g4[q] = (sPart[p][0][r][b] + sPart[p][1][r][b])
                      + (sPart[p][2][r][b] + sPart[p][3][r][b])
                      + fmaf(xv, wih[q], bias[q]);
            }
            float is = fsig(g4[0]);
            float fs = fsig(g4[1]);
            float gs = ftanh(g4[2]);
            float os = fsig(g4[3]);
            float cn = fs * c_loc + is * gs;
            float hn = os * ftanh(cn);
            h_loc = 0.5f * (h_loc + hn);

            // publish h (single fp16) and release this warp immediately
            __half hh = __float2half(h_loc);
            unsigned char* nimg = (unsigned char*)g_Bimg[p ^ 1];
            stcg_u16(nimg + off_h, *(unsigned short*)&hh);
            __syncwarp();
            if (lane == 0) red_rel_add1(mycnt);

            // ---- off-critical-path epilogue ----
            c_loc = 0.5f * (c_loc + cn);
            sOut[b * 4 + u] = h_loc;
            if (write_final && t == T_ - 1) {
                float* o2 = out + (size_t)B_ * T_ * H_;
                o2[b * (2 * H_) + gu]      = h_loc;
                o2[b * (2 * H_) + H_ + gu] = c_loc;
            }
            asm volatile("bar.sync 1, 128;" ::: "memory");

            if (tid < 32) {  // coalesced v4 output store
                const float4 v = *(const float4*)(sOut + tid * 4);
                float* dst = out + ((size_t)tid * T_ + t) * H_ + cta * 4;
                asm volatile("st.global.cs.v4.f32 [%0], {%1,%2,%3,%4};"
                             :: "l"(dst), "f"(v.x), "f"(v.y), "f"(v.z), "f"(v.w));
            }
        }
    }
}

extern "C" void kernel_launch(void* const* d_in, const int* in_sizes, int n_in,
                              void* d_out, int out_size)
{
    const float* x   = (const float*)d_in[0];
    const float* Wih = (const float*)d_in[1];
    const float* Whh = (const float*)d_in[2];
    const float* bih = (const float*)d_in[3];
    const float* bhh = (const float*)d_in[4];
    float* out = (float*)d_out;

    int need = B_ * T_ * H_ + B_ * 2 * H_;
    int write_final = (out_size >= need) ? 1 : 0;

    init_kernel<<<256, 512>>>(x);
    lstm_kernel<<<GRID_, THREADS_>>>(Wih, Whh, bih, bhh, out, write_final);
}